// round 1
// baseline (speedup 1.0000x reference)
#include <cuda_runtime.h>

#define NN 50000
#define EE 800000
#define DD 64

// ---------------- scratch (device globals; no allocation allowed) ----------
__device__ int   g_is64;
__device__ int   g_esrc[EE];
__device__ int   g_edst[EE];
__device__ int   g_deg[NN];
__device__ int   g_fill[NN];
__device__ int   g_rowptr[NN + 1];
__device__ int   g_adj[EE];
__device__ float g_agg[NN * DD];
__device__ float g_h[NN * DD];

// ---------------- zero degree/fill counters --------------------------------
__global__ void k_zero() {
    int i = blockIdx.x * blockDim.x + threadIdx.x;
    if (i < NN) { g_deg[i] = 0; g_fill[i] = 0; }
}

// ---------------- edge dtype detection -------------------------------------
// If edge_index is int64, every odd 32-bit word (high word of a non-negative
// index < 50000) is 0. If int32, odd words are random node indices; the
// probability that 4096 of them are all zero is (1/50000)^4096 ~ 0.
// Only reads words [0, 8192) -- within bounds for both layouts.
__global__ void k_detect(const int* __restrict__ w) {
    __shared__ int s_nz;
    if (threadIdx.x == 0) s_nz = 0;
    __syncthreads();
    int nz = 0;
    for (int k = threadIdx.x; k < 4096; k += 256) nz |= w[2 * k + 1];
    atomicOr(&s_nz, nz);
    __syncthreads();
    if (threadIdx.x == 0) g_is64 = (s_nz == 0) ? 1 : 0;
}

// ---------------- convert edges to int32 + count degrees -------------------
__global__ void k_convert(const int* __restrict__ w) {
    int e = blockIdx.x * blockDim.x + threadIdx.x;
    if (e >= EE) return;
    int src, dst;
    if (g_is64) {
        src = w[2 * e];
        dst = w[2 * (EE + e)];
    } else {
        src = w[e];
        dst = w[EE + e];
    }
    g_esrc[e] = src;
    g_edst[e] = dst;
    atomicAdd(&g_deg[dst], 1);
}

// ---------------- exclusive prefix sum over degrees (single block) ---------
__global__ void k_scan() {
    __shared__ int wsum[32];
    __shared__ int s_carry;
    int tid  = threadIdx.x;
    int lane = tid & 31, wid = tid >> 5;
    if (tid == 0) s_carry = 0;
    __syncthreads();
    for (int base = 0; base < NN; base += 1024) {
        int i = base + tid;
        int v = (i < NN) ? g_deg[i] : 0;
        int xv = v;
        #pragma unroll
        for (int o = 1; o < 32; o <<= 1) {
            int y = __shfl_up_sync(0xffffffffu, xv, o);
            if (lane >= o) xv += y;
        }
        if (lane == 31) wsum[wid] = xv;
        __syncthreads();
        if (tid < 32) {
            int ws = wsum[tid];
            int y = ws;
            #pragma unroll
            for (int o = 1; o < 32; o <<= 1) {
                int z = __shfl_up_sync(0xffffffffu, y, o);
                if (tid >= o) y += z;
            }
            wsum[tid] = y - ws;   // exclusive warp offset
        }
        __syncthreads();
        int incl = xv + wsum[wid];
        if (i < NN) g_rowptr[i] = s_carry + incl - v;  // exclusive scan
        __syncthreads();
        if (tid == 1023) s_carry += incl;
        __syncthreads();
    }
    if (tid == 0) g_rowptr[NN] = s_carry;
}

// ---------------- counting-sort edges into CSR adjacency -------------------
__global__ void k_fill() {
    int e = blockIdx.x * blockDim.x + threadIdx.x;
    if (e >= EE) return;
    int dst = g_edst[e];
    int pos = g_rowptr[dst] + atomicAdd(&g_fill[dst], 1);
    g_adj[pos] = g_esrc[e];
}

// ---------------- mean aggregation: 16 threads/node, float4 lanes ----------
// USE_H = 0: aggregate from xin (layer 1); USE_H = 1: aggregate from g_h.
template <int USE_H>
__global__ void k_agg(const float* __restrict__ xin) {
    int t    = blockIdx.x * blockDim.x + threadIdx.x;
    int node = t >> 4;
    if (node >= NN) return;
    int lane = t & 15;
    const float* in  = USE_H ? (const float*)g_h : xin;
    const float4* in4 = (const float4*)in;
    int start = g_rowptr[node];
    int end   = g_rowptr[node + 1];
    float ax = 0.f, ay = 0.f, az = 0.f, aw = 0.f;
    int i = start;
    // unroll 4 for MLP (L2-latency hiding)
    for (; i + 4 <= end; i += 4) {
        int s0 = g_adj[i], s1 = g_adj[i + 1], s2 = g_adj[i + 2], s3 = g_adj[i + 3];
        float4 v0 = in4[s0 * 16 + lane];
        float4 v1 = in4[s1 * 16 + lane];
        float4 v2 = in4[s2 * 16 + lane];
        float4 v3 = in4[s3 * 16 + lane];
        ax += (v0.x + v1.x) + (v2.x + v3.x);
        ay += (v0.y + v1.y) + (v2.y + v3.y);
        az += (v0.z + v1.z) + (v2.z + v3.z);
        aw += (v0.w + v1.w) + (v2.w + v3.w);
    }
    for (; i < end; ++i) {
        int s = g_adj[i];
        float4 v = in4[s * 16 + lane];
        ax += v.x; ay += v.y; az += v.z; aw += v.w;
    }
    int deg = end - start;
    float inv = 1.0f / (float)(deg > 0 ? deg : 1);
    float4 r;
    r.x = ax * inv; r.y = ay * inv; r.z = az * inv; r.w = aw * inv;
    ((float4*)g_agg)[node * 16 + lane] = r;
}

// ---------------- fused dual-GEMM + bias (+tanh) ---------------------------
// out[n][j] = bias[j] + sum_k agg[n][k]*Wl[j][k] + sum_k xrow[n][k]*Wr[j][k]
// LAYER==0: xrow = xin,  out = g_h, apply tanh.
// LAYER==1: xrow = g_h,  out = outp.
// W resident in SMEM, row padded to 68 floats (16B-aligned, conflict-tamed).
// One thread per output element; float4 over K; persistent grid-stride blocks.
template <int LAYER>
__global__ __launch_bounds__(512) void k_gemm(
    const float* __restrict__ xin, const float* __restrict__ Wl,
    const float* __restrict__ bl, const float* __restrict__ Wr,
    float* __restrict__ outp)
{
    __shared__ float Wl_s[64 * 68];
    __shared__ float Wr_s[64 * 68];
    __shared__ float b_s[64];
    __shared__ float a_s[8 * 64];
    __shared__ float x_s[8 * 64];
    int tid = threadIdx.x;
    for (int idx = tid; idx < 4096; idx += 512) {
        int j = idx >> 6, k = idx & 63;
        Wl_s[j * 68 + k] = Wl[idx];
        Wr_s[j * 68 + k] = Wr[idx];
    }
    if (tid < 64) b_s[tid] = bl[tid];

    const float* xr = (LAYER == 0) ? xin : (const float*)g_h;
    float* out      = (LAYER == 0) ? (float*)g_h : outp;

    int node_l = tid >> 6;   // 0..7
    int j      = tid & 63;
    const float* wl = &Wl_s[j * 68];
    const float* wr = &Wr_s[j * 68];
    __syncthreads();

    for (int tile = blockIdx.x; tile < NN / 8; tile += gridDim.x) {
        int base = tile * 8;
        // stage 8 node rows of agg + x (coalesced float4)
        if (tid < 128)
            ((float4*)a_s)[tid] = ((const float4*)(g_agg + (size_t)base * 64))[tid];
        else if (tid < 256)
            ((float4*)x_s)[tid - 128] = ((const float4*)(xr + (size_t)base * 64))[tid - 128];
        __syncthreads();

        const float* ar = &a_s[node_l * 64];
        const float* xv = &x_s[node_l * 64];
        float s0 = 0.f, s1 = 0.f, s2 = 0.f, s3 = 0.f;
        #pragma unroll
        for (int k = 0; k < 64; k += 4) {
            float4 a  = *(const float4*)&ar[k];
            float4 xx = *(const float4*)&xv[k];
            float4 l  = *(const float4*)&wl[k];
            float4 r  = *(const float4*)&wr[k];
            s0 += a.x * l.x;  s1 += a.y * l.y;  s2 += a.z * l.z;  s3 += a.w * l.w;
            s0 += xx.x * r.x; s1 += xx.y * r.y; s2 += xx.z * r.z; s3 += xx.w * r.w;
        }
        float acc = b_s[j] + ((s0 + s1) + (s2 + s3));
        if (LAYER == 0) acc = tanhf(acc);
        out[(size_t)(base + node_l) * 64 + j] = acc;
        __syncthreads();   // protect a_s/x_s before next tile's staging
    }
}

// ---------------- launch ----------------------------------------------------
extern "C" void kernel_launch(void* const* d_in, const int* in_sizes, int n_in,
                              void* d_out, int out_size) {
    const float* x   = (const float*)d_in[0];
    const int*   ei  = (const int*)d_in[1];
    const float* Wl1 = (const float*)d_in[2];
    const float* bl1 = (const float*)d_in[3];
    const float* Wr1 = (const float*)d_in[4];
    const float* Wl2 = (const float*)d_in[5];
    const float* bl2 = (const float*)d_in[6];
    const float* Wr2 = (const float*)d_in[7];
    float* out = (float*)d_out;

    k_zero<<<(NN + 255) / 256, 256>>>();
    k_detect<<<1, 256>>>(ei);
    k_convert<<<(EE + 255) / 256, 256>>>(ei);
    k_scan<<<1, 1024>>>();
    k_fill<<<(EE + 255) / 256, 256>>>();

    // Layer 1
    k_agg<0><<<(NN * 16 + 255) / 256, 256>>>(x);
    k_gemm<0><<<592, 512>>>(x, Wl1, bl1, Wr1, out);

    // Layer 2
    k_agg<1><<<(NN * 16 + 255) / 256, 256>>>(nullptr);
    k_gemm<1><<<592, 512>>>(nullptr, Wl2, bl2, Wr2, out);
}

// round 4
// speedup vs baseline: 1.0404x; 1.0404x over previous
#include <cuda_runtime.h>

#define NN 50000
#define EE 800000
#define DD 64

// ---------------- scratch (device globals; no allocation allowed) ----------
__device__ int   g_is64;
__device__ int   g_esrc[EE];
__device__ int   g_edst[EE];
__device__ int   g_deg[NN];
__device__ int   g_fill[NN];
__device__ int   g_rowptr[NN + 1];
__device__ int   g_blocksums[64];
__device__ int   g_adj[EE];
__device__ float g_agg[NN * DD];
__device__ float g_h[NN * DD];

#define SCAN_BLOCKS 49   // ceil(50000/1024)

// ---------------- init: zero counters + detect edge dtype ------------------
// Blocks 0..(NB-1) zero deg/fill; last block detects int64-vs-int32 edges.
// If edge_index is int64, every odd 32-bit word (high word of an index
// < 50000) is 0. If int32, odd words are random node ids -> nonzero found.
__global__ void k_init(const int* __restrict__ w, int nzero_blocks) {
    if ((int)blockIdx.x < nzero_blocks) {
        int i = blockIdx.x * blockDim.x + threadIdx.x;
        if (i < NN) { g_deg[i] = 0; g_fill[i] = 0; }
    } else {
        __shared__ int s_nz;
        if (threadIdx.x == 0) s_nz = 0;
        __syncthreads();
        int nz = 0;
        for (int k = threadIdx.x; k < 4096; k += blockDim.x) nz |= w[2 * k + 1];
        atomicOr(&s_nz, nz);
        __syncthreads();
        if (threadIdx.x == 0) g_is64 = (s_nz == 0) ? 1 : 0;
    }
}

// ---------------- convert edges to int32 + count degrees -------------------
__global__ void k_convert(const int* __restrict__ w) {
    int e = blockIdx.x * blockDim.x + threadIdx.x;
    if (e >= EE) return;
    int src, dst;
    if (g_is64) {
        src = w[2 * e];
        dst = w[2 * (EE + e)];
    } else {
        src = w[e];
        dst = w[EE + e];
    }
    g_esrc[e] = src;
    g_edst[e] = dst;
    atomicAdd(&g_deg[dst], 1);
}

// ---------------- 3-phase parallel exclusive scan of degrees ---------------
// Phase 1: per-block (1024-wide) exclusive scan; block sums to g_blocksums.
__global__ __launch_bounds__(1024) void k_scan1() {
    __shared__ int wsum[32];
    int tid  = threadIdx.x;
    int lane = tid & 31, wid = tid >> 5;
    int i = blockIdx.x * 1024 + tid;
    int v = (i < NN) ? g_deg[i] : 0;
    int xv = v;
    #pragma unroll
    for (int o = 1; o < 32; o <<= 1) {
        int y = __shfl_up_sync(0xffffffffu, xv, o);
        if (lane >= o) xv += y;
    }
    if (lane == 31) wsum[wid] = xv;
    __syncthreads();
    if (tid < 32) {
        int ws = wsum[tid];
        int y = ws;
        #pragma unroll
        for (int o = 1; o < 32; o <<= 1) {
            int z = __shfl_up_sync(0xffffffffu, y, o);
            if (tid >= o) y += z;
        }
        wsum[tid] = y - ws;   // exclusive warp offset
    }
    __syncthreads();
    int excl = xv - v + wsum[wid];
    if (i < NN) g_rowptr[i] = excl;
    if (tid == 1023) g_blocksums[blockIdx.x] = excl + v;  // block total
}

// Phase 2: single 64-thread block scans the 49 block sums (exclusive),
// and writes the grand total to g_rowptr[NN].
__global__ void k_scan2() {
    __shared__ int s[64];
    int t = threadIdx.x;
    int v = (t < SCAN_BLOCKS) ? g_blocksums[t] : 0;
    s[t] = v;
    __syncthreads();
    #pragma unroll
    for (int off = 1; off < 64; off <<= 1) {
        int y = (t >= off) ? s[t - off] : 0;
        __syncthreads();
        s[t] += y;
        __syncthreads();
    }
    if (t < SCAN_BLOCKS) g_blocksums[t] = s[t] - v;   // exclusive
    if (t == 0) g_rowptr[NN] = s[63];                 // total = EE
}

// Phase 3: add block offsets.
__global__ __launch_bounds__(1024) void k_scan3() {
    int i = blockIdx.x * 1024 + threadIdx.x;
    if (i < NN) g_rowptr[i] += g_blocksums[blockIdx.x];
}

// ---------------- counting-sort edges into CSR adjacency -------------------
__global__ void k_fill() {
    int e = blockIdx.x * blockDim.x + threadIdx.x;
    if (e >= EE) return;
    int dst = g_edst[e];
    int pos = g_rowptr[dst] + atomicAdd(&g_fill[dst], 1);
    g_adj[pos] = g_esrc[e];
}

// ---------------- mean aggregation: 16 threads/node, float4 lanes ----------
template <int USE_H>
__global__ void k_agg(const float* __restrict__ xin) {
    int t    = blockIdx.x * blockDim.x + threadIdx.x;
    int node = t >> 4;
    if (node >= NN) return;
    int lane = t & 15;
    const float* in  = USE_H ? (const float*)g_h : xin;
    const float4* in4 = (const float4*)in;
    int start = g_rowptr[node];
    int end   = g_rowptr[node + 1];
    float ax = 0.f, ay = 0.f, az = 0.f, aw = 0.f;
    int i = start;
    for (; i + 4 <= end; i += 4) {
        int s0 = g_adj[i], s1 = g_adj[i + 1], s2 = g_adj[i + 2], s3 = g_adj[i + 3];
        float4 v0 = in4[s0 * 16 + lane];
        float4 v1 = in4[s1 * 16 + lane];
        float4 v2 = in4[s2 * 16 + lane];
        float4 v3 = in4[s3 * 16 + lane];
        ax += (v0.x + v1.x) + (v2.x + v3.x);
        ay += (v0.y + v1.y) + (v2.y + v3.y);
        az += (v0.z + v1.z) + (v2.z + v3.z);
        aw += (v0.w + v1.w) + (v2.w + v3.w);
    }
    for (; i < end; ++i) {
        int s = g_adj[i];
        float4 v = in4[s * 16 + lane];
        ax += v.x; ay += v.y; az += v.z; aw += v.w;
    }
    int deg = end - start;
    float inv = 1.0f / (float)(deg > 0 ? deg : 1);
    float4 r;
    r.x = ax * inv; r.y = ay * inv; r.z = az * inv; r.w = aw * inv;
    ((float4*)g_agg)[node * 16 + lane] = r;
}

// ---------------- fused dual-GEMM + bias (+tanh), f32x2 packed FMA ---------
// out[n][j] = bias[j] + sum_k agg[n][k]*Wl[j][k] + sum_k xrow[n][k]*Wr[j][k]
// LAYER==0: xrow = xin,  out = g_h, apply tanh.
// LAYER==1: xrow = g_h,  out = outp.
// W rows padded to 68 floats: LDS.128 phases hit all 32 banks exactly once.
template <int LAYER>
__global__ __launch_bounds__(512) void k_gemm(
    const float* __restrict__ xin, const float* __restrict__ Wl,
    const float* __restrict__ bl, const float* __restrict__ Wr,
    float* __restrict__ outp)
{
    __shared__ float Wl_s[64 * 68];
    __shared__ float Wr_s[64 * 68];
    __shared__ float b_s[64];
    __shared__ float a_s[8 * 64];
    __shared__ float x_s[8 * 64];
    int tid = threadIdx.x;
    for (int idx = tid; idx < 4096; idx += 512) {
        int j = idx >> 6, k = idx & 63;
        Wl_s[j * 68 + k] = Wl[idx];
        Wr_s[j * 68 + k] = Wr[idx];
    }
    if (tid < 64) b_s[tid] = bl[tid];

    const float* xr = (LAYER == 0) ? xin : (const float*)g_h;
    float* out      = (LAYER == 0) ? (float*)g_h : outp;

    int node_l = tid >> 6;   // 0..7
    int j      = tid & 63;
    const float* wl = &Wl_s[j * 68];
    const float* wr = &Wr_s[j * 68];
    __syncthreads();

    for (int tile = blockIdx.x; tile < NN / 8; tile += gridDim.x) {
        int base = tile * 8;
        if (tid < 128)
            ((float4*)a_s)[tid] = ((const float4*)(g_agg + (size_t)base * 64))[tid];
        else if (tid < 256)
            ((float4*)x_s)[tid - 128] = ((const float4*)(xr + (size_t)base * 64))[tid - 128];
        __syncthreads();

        const float* ar = &a_s[node_l * 64];
        const float* xv = &x_s[node_l * 64];
        unsigned long long p0 = 0ull, p1 = 0ull;   // packed f32x2 accumulators
        #pragma unroll
        for (int k = 0; k < 64; k += 4) {
            ulonglong2 A = *(const ulonglong2*)&ar[k];
            ulonglong2 X = *(const ulonglong2*)&xv[k];
            ulonglong2 L = *(const ulonglong2*)&wl[k];
            ulonglong2 R = *(const ulonglong2*)&wr[k];
            asm("fma.rn.f32x2 %0, %1, %2, %0;" : "+l"(p0) : "l"(A.x), "l"(L.x));
            asm("fma.rn.f32x2 %0, %1, %2, %0;" : "+l"(p1) : "l"(A.y), "l"(L.y));
            asm("fma.rn.f32x2 %0, %1, %2, %0;" : "+l"(p0) : "l"(X.x), "l"(R.x));
            asm("fma.rn.f32x2 %0, %1, %2, %0;" : "+l"(p1) : "l"(X.y), "l"(R.y));
        }
        float s0, s1, s2, s3;
        asm("mov.b64 {%0,%1}, %2;" : "=f"(s0), "=f"(s1) : "l"(p0));
        asm("mov.b64 {%0,%1}, %2;" : "=f"(s2), "=f"(s3) : "l"(p1));
        float acc = b_s[j] + ((s0 + s1) + (s2 + s3));
        if (LAYER == 0) acc = tanhf(acc);
        out[(size_t)(base + node_l) * 64 + j] = acc;
        __syncthreads();
    }
}

// ---------------- launch ----------------------------------------------------
extern "C" void kernel_launch(void* const* d_in, const int* in_sizes, int n_in,
                              void* d_out, int out_size) {
    const float* x   = (const float*)d_in[0];
    const int*   ei  = (const int*)d_in[1];
    const float* Wl1 = (const float*)d_in[2];
    const float* bl1 = (const float*)d_in[3];
    const float* Wr1 = (const float*)d_in[4];
    const float* Wl2 = (const float*)d_in[5];
    const float* bl2 = (const float*)d_in[6];
    const float* Wr2 = (const float*)d_in[7];
    float* out = (float*)d_out;

    int nzero_blocks = (NN + 255) / 256;
    k_init<<<nzero_blocks + 1, 256>>>(ei, nzero_blocks);
    k_convert<<<(EE + 255) / 256, 256>>>(ei);
    k_scan1<<<SCAN_BLOCKS, 1024>>>();
    k_scan2<<<1, 64>>>();
    k_scan3<<<SCAN_BLOCKS, 1024>>>();
    k_fill<<<(EE + 255) / 256, 256>>>();

    // Layer 1
    k_agg<0><<<(NN * 16 + 255) / 256, 256>>>(x);
    k_gemm<0><<<625, 512>>>(x, Wl1, bl1, Wr1, out);

    // Layer 2
    k_agg<1><<<(NN * 16 + 255) / 256, 256>>>(nullptr);
    k_gemm<1><<<625, 512>>>(nullptr, Wl2, bl2, Wr2, out);
}

// round 5
// speedup vs baseline: 1.5267x; 1.4674x over previous
#include <cuda_runtime.h>

#define NN 50000
#define EE 800000
#define DD 64

typedef unsigned long long ull;

// ---------------- scratch (device globals; no allocation allowed) ----------
__device__ int   g_is64;
__device__ int   g_esrc[EE];
__device__ int   g_edst[EE];
__device__ int   g_deg[NN];
__device__ int   g_fill[NN];
__device__ int   g_rowptr[NN + 1];
__device__ int   g_blocksums[64];
__device__ int   g_adj[EE];
__device__ float g_agg[NN * DD];
__device__ float g_h[NN * DD];

#define SCAN_BLOCKS 49   // ceil(50000/1024)
#define GEMM_BLOCKS 888  // 148 SMs * 6 blocks
#define GEMM_CHUNK  57   // ceil(50000/888)

// ---------------- init: zero counters + detect edge dtype ------------------
__global__ void k_init(const int* __restrict__ w, int nzero_blocks) {
    if ((int)blockIdx.x < nzero_blocks) {
        int i = blockIdx.x * blockDim.x + threadIdx.x;
        if (i < NN) { g_deg[i] = 0; g_fill[i] = 0; }
    } else {
        __shared__ int s_nz;
        if (threadIdx.x == 0) s_nz = 0;
        __syncthreads();
        int nz = 0;
        for (int k = threadIdx.x; k < 4096; k += blockDim.x) nz |= w[2 * k + 1];
        atomicOr(&s_nz, nz);
        __syncthreads();
        if (threadIdx.x == 0) g_is64 = (s_nz == 0) ? 1 : 0;
    }
}

// ---------------- convert edges to int32 + count degrees -------------------
__global__ void k_convert(const int* __restrict__ w) {
    int e = blockIdx.x * blockDim.x + threadIdx.x;
    if (e >= EE) return;
    int src, dst;
    if (g_is64) {
        src = w[2 * e];
        dst = w[2 * (EE + e)];
    } else {
        src = w[e];
        dst = w[EE + e];
    }
    g_esrc[e] = src;
    g_edst[e] = dst;
    atomicAdd(&g_deg[dst], 1);
}

// ---------------- 3-phase parallel exclusive scan of degrees ---------------
__global__ __launch_bounds__(1024) void k_scan1() {
    __shared__ int wsum[32];
    int tid  = threadIdx.x;
    int lane = tid & 31, wid = tid >> 5;
    int i = blockIdx.x * 1024 + tid;
    int v = (i < NN) ? g_deg[i] : 0;
    int xv = v;
    #pragma unroll
    for (int o = 1; o < 32; o <<= 1) {
        int y = __shfl_up_sync(0xffffffffu, xv, o);
        if (lane >= o) xv += y;
    }
    if (lane == 31) wsum[wid] = xv;
    __syncthreads();
    if (tid < 32) {
        int ws = wsum[tid];
        int y = ws;
        #pragma unroll
        for (int o = 1; o < 32; o <<= 1) {
            int z = __shfl_up_sync(0xffffffffu, y, o);
            if (tid >= o) y += z;
        }
        wsum[tid] = y - ws;
    }
    __syncthreads();
    int excl = xv - v + wsum[wid];
    if (i < NN) g_rowptr[i] = excl;
    if (tid == 1023) g_blocksums[blockIdx.x] = excl + v;
}

__global__ void k_scan2() {
    __shared__ int s[64];
    int t = threadIdx.x;
    int v = (t < SCAN_BLOCKS) ? g_blocksums[t] : 0;
    s[t] = v;
    __syncthreads();
    #pragma unroll
    for (int off = 1; off < 64; off <<= 1) {
        int y = (t >= off) ? s[t - off] : 0;
        __syncthreads();
        s[t] += y;
        __syncthreads();
    }
    if (t < SCAN_BLOCKS) g_blocksums[t] = s[t] - v;
    if (t == 0) g_rowptr[NN] = s[63];
}

__global__ __launch_bounds__(1024) void k_scan3() {
    int i = blockIdx.x * 1024 + threadIdx.x;
    if (i < NN) g_rowptr[i] += g_blocksums[blockIdx.x];
}

// ---------------- counting-sort edges into CSR adjacency -------------------
__global__ void k_fill() {
    int e = blockIdx.x * blockDim.x + threadIdx.x;
    if (e >= EE) return;
    int dst = g_edst[e];
    int pos = g_rowptr[dst] + atomicAdd(&g_fill[dst], 1);
    g_adj[pos] = g_esrc[e];
}

// ---------------- mean aggregation: 16 threads/node, float4 lanes ----------
template <int USE_H>
__global__ void k_agg(const float* __restrict__ xin) {
    int t    = blockIdx.x * blockDim.x + threadIdx.x;
    int node = t >> 4;
    if (node >= NN) return;
    int lane = t & 15;
    const float* in  = USE_H ? (const float*)g_h : xin;
    const float4* in4 = (const float4*)in;
    int start = g_rowptr[node];
    int end   = g_rowptr[node + 1];
    float ax = 0.f, ay = 0.f, az = 0.f, aw = 0.f;
    int i = start;
    for (; i + 4 <= end; i += 4) {
        int s0 = g_adj[i], s1 = g_adj[i + 1], s2 = g_adj[i + 2], s3 = g_adj[i + 3];
        float4 v0 = in4[s0 * 16 + lane];
        float4 v1 = in4[s1 * 16 + lane];
        float4 v2 = in4[s2 * 16 + lane];
        float4 v3 = in4[s3 * 16 + lane];
        ax += (v0.x + v1.x) + (v2.x + v3.x);
        ay += (v0.y + v1.y) + (v2.y + v3.y);
        az += (v0.z + v1.z) + (v2.z + v3.z);
        aw += (v0.w + v1.w) + (v2.w + v3.w);
    }
    for (; i < end; ++i) {
        int s = g_adj[i];
        float4 v = in4[s * 16 + lane];
        ax += v.x; ay += v.y; az += v.z; aw += v.w;
    }
    int deg = end - start;
    float inv = 1.0f / (float)(deg > 0 ? deg : 1);
    float4 r;
    r.x = ax * inv; r.y = ay * inv; r.z = az * inv; r.w = aw * inv;
    ((float4*)g_agg)[node * 16 + lane] = r;
}

// ---------------- dual-GEMM: register-resident W, broadcast x --------------
// 64 threads/block; thread j holds Wl[j][:], Wr[j][:] packed as f32x2 regs.
// Per node: stage agg/x rows to smem (coalesced), read back broadcast,
// 64 packed FMAs per thread. Double-buffered, one bar per node.
// LAYER==0: xrow = xin, out = g_h, tanh. LAYER==1: xrow = g_h, out = outp.
template <int LAYER>
__global__ __launch_bounds__(64) void k_gemm(
    const float* __restrict__ xin, const float* __restrict__ Wl,
    const float* __restrict__ bl, const float* __restrict__ Wr,
    float* __restrict__ outp)
{
    __shared__ __align__(16) float sA[2][64];
    __shared__ __align__(16) float sX[2][64];
    int j = threadIdx.x;

    // W rows -> registers (packed f32x2 along k)
    ull wl[32], wr[32];
    const ull* Wl8 = (const ull*)Wl;
    const ull* Wr8 = (const ull*)Wr;
    #pragma unroll
    for (int q = 0; q < 32; q++) {
        wl[q] = Wl8[j * 32 + q];
        wr[q] = Wr8[j * 32 + q];
    }
    float bj = bl[j];

    const float* xr = (LAYER == 0) ? xin : (const float*)g_h;
    float* out      = (LAYER == 0) ? (float*)g_h : outp;

    int n     = blockIdx.x * GEMM_CHUNK;
    int n_end = n + GEMM_CHUNK;
    if (n_end > NN) n_end = NN;
    if (n >= n_end) return;

    // prime buffer 0
    sA[0][j] = g_agg[(size_t)n * 64 + j];
    sX[0][j] = xr[(size_t)n * 64 + j];
    __syncthreads();

    int buf = 0;
    for (; n < n_end; ++n) {
        if (n + 1 < n_end) {
            sA[buf ^ 1][j] = g_agg[(size_t)(n + 1) * 64 + j];
            sX[buf ^ 1][j] = xr[(size_t)(n + 1) * 64 + j];
        }
        const ulonglong2* pa = (const ulonglong2*)sA[buf];
        const ulonglong2* px = (const ulonglong2*)sX[buf];
        ull a0 = 0ull, a1 = 0ull, a2 = 0ull, a3 = 0ull;
        #pragma unroll
        for (int q = 0; q < 16; q++) {
            ulonglong2 av = pa[q];
            asm("fma.rn.f32x2 %0, %1, %2, %0;" : "+l"(a0) : "l"(av.x), "l"(wl[2 * q]));
            asm("fma.rn.f32x2 %0, %1, %2, %0;" : "+l"(a1) : "l"(av.y), "l"(wl[2 * q + 1]));
        }
        #pragma unroll
        for (int q = 0; q < 16; q++) {
            ulonglong2 xv = px[q];
            asm("fma.rn.f32x2 %0, %1, %2, %0;" : "+l"(a2) : "l"(xv.x), "l"(wr[2 * q]));
            asm("fma.rn.f32x2 %0, %1, %2, %0;" : "+l"(a3) : "l"(xv.y), "l"(wr[2 * q + 1]));
        }
        float f0, f1, f2, f3, f4, f5, f6, f7;
        asm("mov.b64 {%0,%1}, %2;" : "=f"(f0), "=f"(f1) : "l"(a0));
        asm("mov.b64 {%0,%1}, %2;" : "=f"(f2), "=f"(f3) : "l"(a1));
        asm("mov.b64 {%0,%1}, %2;" : "=f"(f4), "=f"(f5) : "l"(a2));
        asm("mov.b64 {%0,%1}, %2;" : "=f"(f6), "=f"(f7) : "l"(a3));
        float acc = bj + (((f0 + f1) + (f2 + f3)) + ((f4 + f5) + (f6 + f7)));
        if (LAYER == 0) acc = tanhf(acc);
        out[(size_t)n * 64 + j] = acc;
        __syncthreads();
        buf ^= 1;
    }
}

// ---------------- launch ----------------------------------------------------
extern "C" void kernel_launch(void* const* d_in, const int* in_sizes, int n_in,
                              void* d_out, int out_size) {
    const float* x   = (const float*)d_in[0];
    const int*   ei  = (const int*)d_in[1];
    const float* Wl1 = (const float*)d_in[2];
    const float* bl1 = (const float*)d_in[3];
    const float* Wr1 = (const float*)d_in[4];
    const float* Wl2 = (const float*)d_in[5];
    const float* bl2 = (const float*)d_in[6];
    const float* Wr2 = (const float*)d_in[7];
    float* out = (float*)d_out;

    int nzero_blocks = (NN + 255) / 256;
    k_init<<<nzero_blocks + 1, 256>>>(ei, nzero_blocks);
    k_convert<<<(EE + 255) / 256, 256>>>(ei);
    k_scan1<<<SCAN_BLOCKS, 1024>>>();
    k_scan2<<<1, 64>>>();
    k_scan3<<<SCAN_BLOCKS, 1024>>>();
    k_fill<<<(EE + 255) / 256, 256>>>();

    // Layer 1
    k_agg<0><<<(NN * 16 + 255) / 256, 256>>>(x);
    k_gemm<0><<<GEMM_BLOCKS, 64>>>(x, Wl1, bl1, Wr1, out);

    // Layer 2
    k_agg<1><<<(NN * 16 + 255) / 256, 256>>>(nullptr);
    k_gemm<1><<<GEMM_BLOCKS, 64>>>(nullptr, Wl2, bl2, Wr2, out);
}

// round 9
// speedup vs baseline: 1.5439x; 1.0113x over previous
#include <cuda_runtime.h>

#define NN 50000
#define EE 800000
#define DD 64

typedef unsigned long long ull;

// ---------------- scratch (device globals; no allocation allowed) ----------
__device__ int   g_deg[NN];
__device__ int   g_fill[NN];
__device__ int   g_rowptr[NN + 1];
__device__ ull   g_scan_desc[64];   // (status<<32)|value; 0=invalid,1=agg,2=prefix
__device__ int   g_adj[EE];
__device__ float g_agg[NN * DD];
__device__ float g_h[NN * DD];

#define SCAN_BLOCKS 49   // ceil(50000/1024)
#define EDGE_BLOCKS 3125 // EE / 256 exactly
#define GEMM_BLOCKS 888  // 148 SMs * 6 blocks
#define GEMM_CHUNK  57   // ceil(50000/888)

// ---------------- per-block edge dtype detection ---------------------------
// int64 edges -> all odd 32-bit words in [0,1024) are high words of indices
// < 50000, i.e. zero. int32 edges -> they are random node ids; P(all 512
// sampled words zero) ~ (2e-5)^512 = 0. Reads words [0,1024): in range for
// both layouts. Returns 1 if int64. Uses __syncthreads_or (all threads).
__device__ __forceinline__ int detect_is64(const int* __restrict__ w) {
    int t = threadIdx.x;            // blockDim.x == 256
    int nz = w[2 * t + 1] | w[2 * (t + 256) + 1];
    return __syncthreads_or(nz) ? 0 : 1;
}

// ---------------- pass 1: count degrees ------------------------------------
__global__ __launch_bounds__(256) void k_convert(const int* __restrict__ w) {
    int is64 = detect_is64(w);
    int e = blockIdx.x * 256 + threadIdx.x;       // always < EE
    int dst = is64 ? w[2 * (EE + e)] : w[EE + e];
    atomicAdd(&g_deg[dst], 1);
}

// ---------------- single-kernel decoupled-lookback exclusive scan ----------
__global__ __launch_bounds__(1024) void k_scan() {
    __shared__ int wsum[32];
    __shared__ int s_prefix;
    int tid  = threadIdx.x;
    int lane = tid & 31, wid = tid >> 5;
    int b = blockIdx.x;
    int i = b * 1024 + tid;
    int v = (i < NN) ? g_deg[i] : 0;
    int xv = v;
    #pragma unroll
    for (int o = 1; o < 32; o <<= 1) {
        int y = __shfl_up_sync(0xffffffffu, xv, o);
        if (lane >= o) xv += y;
    }
    if (lane == 31) wsum[wid] = xv;
    __syncthreads();
    if (tid < 32) {
        int ws = wsum[tid];
        int y = ws;
        #pragma unroll
        for (int o = 1; o < 32; o <<= 1) {
            int z = __shfl_up_sync(0xffffffffu, y, o);
            if (tid >= o) y += z;
        }
        wsum[tid] = y - ws;
    }
    __syncthreads();
    int excl  = xv - v + wsum[wid];          // block-local exclusive
    int total = 0;
    if (tid == 1023) total = excl + v;        // block aggregate (last thread)

    // thread 1023 publishes + looks back (all 49 blocks are wave-1 resident)
    if (tid == 1023) {
        if (b == 0) {
            atomicExch(&g_scan_desc[0], (2ull << 32) | (unsigned)total);
            s_prefix = 0;
        } else {
            atomicExch(&g_scan_desc[b], (1ull << 32) | (unsigned)total);
            int running = 0;
            for (int p = b - 1; p >= 0; --p) {
                ull d;
                do { d = atomicAdd(&g_scan_desc[p], 0ull); } while ((d >> 32) == 0);
                running += (int)(unsigned)d;
                if ((d >> 32) == 2ull) break;
            }
            atomicExch(&g_scan_desc[b], (2ull << 32) | (unsigned)(running + total));
            s_prefix = running;
        }
    }
    __syncthreads();
    int pfx = s_prefix;
    if (i < NN) g_rowptr[i] = pfx + excl;
    if (b == SCAN_BLOCKS - 1 && tid == 1023) g_rowptr[NN] = pfx + total;
}

// ---------------- pass 2: counting-sort edges into CSR ---------------------
__global__ __launch_bounds__(256) void k_fill(const int* __restrict__ w) {
    int is64 = detect_is64(w);
    int e = blockIdx.x * 256 + threadIdx.x;       // always < EE
    int src, dst;
    if (is64) { src = w[2 * e]; dst = w[2 * (EE + e)]; }
    else      { src = w[e];     dst = w[EE + e]; }
    int pos = g_rowptr[dst] + atomicAdd(&g_fill[dst], 1);
    g_adj[pos] = src;
}

// ---------------- mean aggregation: 16 threads/node, float4 lanes ----------
// USE_H==0 additionally re-zeroes deg/fill/scan state for the next replay
// (they are dead at this point; __device__ globals start zeroed, so the
// first call is correct too).
template <int USE_H>
__global__ void k_agg(const float* __restrict__ xin) {
    int t = blockIdx.x * blockDim.x + threadIdx.x;
    if (USE_H == 0) {
        if (t < NN) { g_deg[t] = 0; g_fill[t] = 0; }
        if (t < 64) g_scan_desc[t] = 0ull;
    }
    int node = t >> 4;
    if (node >= NN) return;
    int lane = t & 15;
    const float* in  = USE_H ? (const float*)g_h : xin;
    const float4* in4 = (const float4*)in;
    int start = g_rowptr[node];
    int end   = g_rowptr[node + 1];
    float ax = 0.f, ay = 0.f, az = 0.f, aw = 0.f;
    int i = start;
    for (; i + 4 <= end; i += 4) {
        int s0 = g_adj[i], s1 = g_adj[i + 1], s2 = g_adj[i + 2], s3 = g_adj[i + 3];
        float4 v0 = in4[s0 * 16 + lane];
        float4 v1 = in4[s1 * 16 + lane];
        float4 v2 = in4[s2 * 16 + lane];
        float4 v3 = in4[s3 * 16 + lane];
        ax += (v0.x + v1.x) + (v2.x + v3.x);
        ay += (v0.y + v1.y) + (v2.y + v3.y);
        az += (v0.z + v1.z) + (v2.z + v3.z);
        aw += (v0.w + v1.w) + (v2.w + v3.w);
    }
    for (; i < end; ++i) {
        int s = g_adj[i];
        float4 v = in4[s * 16 + lane];
        ax += v.x; ay += v.y; az += v.z; aw += v.w;
    }
    int deg = end - start;
    float inv = 1.0f / (float)(deg > 0 ? deg : 1);
    float4 r;
    r.x = ax * inv; r.y = ay * inv; r.z = az * inv; r.w = aw * inv;
    ((float4*)g_agg)[node * 16 + lane] = r;
}

// ---------------- dual-GEMM: register-resident W, broadcast x --------------
template <int LAYER>
__global__ __launch_bounds__(64) void k_gemm(
    const float* __restrict__ xin, const float* __restrict__ Wl,
    const float* __restrict__ bl, const float* __restrict__ Wr,
    float* __restrict__ outp)
{
    __shared__ __align__(16) float sA[2][64];
    __shared__ __align__(16) float sX[2][64];
    int j = threadIdx.x;

    ull wl[32], wr[32];
    const ull* Wl8 = (const ull*)Wl;
    const ull* Wr8 = (const ull*)Wr;
    #pragma unroll
    for (int q = 0; q < 32; q++) {
        wl[q] = Wl8[j * 32 + q];
        wr[q] = Wr8[j * 32 + q];
    }
    float bj = bl[j];

    const float* xr = (LAYER == 0) ? xin : (const float*)g_h;
    float* out      = (LAYER == 0) ? (float*)g_h : outp;

    int n     = blockIdx.x * GEMM_CHUNK;
    int n_end = n + GEMM_CHUNK;
    if (n_end > NN) n_end = NN;
    if (n >= n_end) return;

    sA[0][j] = g_agg[(size_t)n * 64 + j];
    sX[0][j] = xr[(size_t)n * 64 + j];
    __syncthreads();

    int buf = 0;
    for (; n < n_end; ++n) {
        if (n + 1 < n_end) {
            sA[buf ^ 1][j] = g_agg[(size_t)(n + 1) * 64 + j];
            sX[buf ^ 1][j] = xr[(size_t)(n + 1) * 64 + j];
        }
        const ulonglong2* pa = (const ulonglong2*)sA[buf];
        const ulonglong2* px = (const ulonglong2*)sX[buf];
        ull a0 = 0ull, a1 = 0ull, a2 = 0ull, a3 = 0ull;
        #pragma unroll
        for (int q = 0; q < 16; q++) {
            ulonglong2 av = pa[q];
            asm("fma.rn.f32x2 %0, %1, %2, %0;" : "+l"(a0) : "l"(av.x), "l"(wl[2 * q]));
            asm("fma.rn.f32x2 %0, %1, %2, %0;" : "+l"(a1) : "l"(av.y), "l"(wl[2 * q + 1]));
        }
        #pragma unroll
        for (int q = 0; q < 16; q++) {
            ulonglong2 xv = px[q];
            asm("fma.rn.f32x2 %0, %1, %2, %0;" : "+l"(a2) : "l"(xv.x), "l"(wr[2 * q]));
            asm("fma.rn.f32x2 %0, %1, %2, %0;" : "+l"(a3) : "l"(xv.y), "l"(wr[2 * q + 1]));
        }
        float f0, f1, f2, f3, f4, f5, f6, f7;
        asm("mov.b64 {%0,%1}, %2;" : "=f"(f0), "=f"(f1) : "l"(a0));
        asm("mov.b64 {%0,%1}, %2;" : "=f"(f2), "=f"(f3) : "l"(a1));
        asm("mov.b64 {%0,%1}, %2;" : "=f"(f4), "=f"(f5) : "l"(a2));
        asm("mov.b64 {%0,%1}, %2;" : "=f"(f6), "=f"(f7) : "l"(a3));
        float acc = bj + (((f0 + f1) + (f2 + f3)) + ((f4 + f5) + (f6 + f7)));
        if (LAYER == 0) acc = tanhf(acc);
        out[(size_t)n * 64 + j] = acc;
        __syncthreads();
        buf ^= 1;
    }
}

// ---------------- launch ----------------------------------------------------
extern "C" void kernel_launch(void* const* d_in, const int* in_sizes, int n_in,
                              void* d_out, int out_size) {
    const float* x   = (const float*)d_in[0];
    const int*   ei  = (const int*)d_in[1];
    const float* Wl1 = (const float*)d_in[2];
    const float* bl1 = (const float*)d_in[3];
    const float* Wr1 = (const float*)d_in[4];
    const float* Wl2 = (const float*)d_in[5];
    const float* bl2 = (const float*)d_in[6];
    const float* Wr2 = (const float*)d_in[7];
    float* out = (float*)d_out;

    k_convert<<<EDGE_BLOCKS, 256>>>(ei);
    k_scan<<<SCAN_BLOCKS, 1024>>>();
    k_fill<<<EDGE_BLOCKS, 256>>>(ei);

    // Layer 1
    k_agg<0><<<EDGE_BLOCKS, 256>>>(x);          // 800000 threads = NN*16
    k_gemm<0><<<GEMM_BLOCKS, 64>>>(x, Wl1, bl1, Wr1, out);

    // Layer 2
    k_agg<1><<<EDGE_BLOCKS, 256>>>(nullptr);
    k_gemm<1><<<GEMM_BLOCKS, 64>>>(nullptr, Wl2, bl2, Wr2, out);
}